// round 14
// baseline (speedup 1.0000x reference)
#include <cuda_runtime.h>
#include <math.h>

#define B_ROWS 128
#define V_COLS 128256
#define V4 (V_COLS / 4)          // 32064 float4 per row
#define SPLIT 6                  // 768 CTAs -> proven best geometry
#define SEG_Q (V4 / SPLIT)       // 5344 float4 per segment (exact)
#define THREADS 256
#define PF_DIST 8                // prefetch 8 iterations (32KB/CTA-stride) ahead

// Per-(row,segment) partials; counter self-resets -> graph-replay safe.
__device__ unsigned long long d_part_g[B_ROWS * SPLIT];
__device__ unsigned long long d_part_s[B_ROWS * SPLIT];
__device__ int d_count[B_ROWS];

// Streaming load with 256B L2 fetch granularity.
__device__ __forceinline__ float4 ldg_stream256(const float4* p) {
    float4 v;
    asm("ld.global.nc.L2::256B.v4.f32 {%0,%1,%2,%3}, [%4];"
        : "=f"(v.x), "=f"(v.y), "=f"(v.z), "=f"(v.w) : "l"(p));
    return v;
}

__device__ __forceinline__ void prefetch_l2(const float4* p) {
    asm volatile("prefetch.global.L2 [%0];" :: "l"(p));
}

// Pack (value, index) so 64-bit unsigned max == (max value, then MIN index)
__device__ __forceinline__ unsigned long long pack_key(float v, int idx) {
    unsigned int b = __float_as_uint(v);
    b = (b & 0x80000000u) ? ~b : (b | 0x80000000u);   // order-preserving map
    return ((unsigned long long)b << 32) | (unsigned int)(~idx);
}

__device__ __forceinline__ unsigned long long kmax64(unsigned long long a,
                                                     unsigned long long b) {
    return a > b ? a : b;
}

// w = -log(uc), RELATIVE-accurate on [1e-10, 1-1e-7] (proven R5 form):
//  - u <= 0.96: MUFU lg2 (w >= 0.0408 -> rel err <= ~8e-6)
//  - u  > 0.96: 4-term log1p poly on f = u-1 (rel err <= 5e-7)
__device__ __forceinline__ float neg_log_acc(float uc) {
    float w_m = -__logf(uc);
    float f = uc - 1.0f;
    float p = -0.25f;
    p = fmaf(p, f, 0.333333333f);
    p = fmaf(p, f, -0.5f);
    float w_p = -fmaf(f * f, p, f);             // -log1p(f)
    return (uc > 0.96f) ? w_p : w_m;
}

__device__ __forceinline__ float score1(float x, float uv, float inv) {
    const float U_LO = 1e-10f;
    const float U_HI = __uint_as_float(0x3F7FFFFEu);   // float(1 - 1e-7)
    float uc = fminf(fmaxf(uv, U_LO), U_HI);
    float w  = neg_log_acc(uc);
    float g  = -__logf(w);
    return fmaf(x, inv, g);
}

// 4 independent scores, tree-reduced (strict > keeps lower index), one update.
__device__ __forceinline__ void body4(float4 l4, float4 u4, int base, float inv,
                                      float& bs, int& bsi) {
    float v0 = score1(l4.x, u4.x, inv);
    float v1 = score1(l4.y, u4.y, inv);
    float v2 = score1(l4.z, u4.z, inv);
    float v3 = score1(l4.w, u4.w, inv);

    float m01 = v0; int i01 = 0;
    if (v1 > m01) { m01 = v1; i01 = 1; }
    float m23 = v2; int i23 = 2;
    if (v3 > m23) { m23 = v3; i23 = 3; }
    float m = m01;  int im = i01;
    if (m23 > m)  { m = m23;  im = i23; }

    if (m > bs) { bs = m; bsi = base + im; }
}

__global__ __launch_bounds__(THREADS, 6)
void sampler_fused_kernel(const float* __restrict__ logits,
                          const float* __restrict__ temps,
                          const float* __restrict__ u,
                          float* __restrict__ out) {
    const int seg = blockIdx.x;
    const int row = blockIdx.y;

    const float4* __restrict__ lg = reinterpret_cast<const float4*>(logits) + (size_t)row * V4;
    const float4* __restrict__ uu = reinterpret_cast<const float4*>(u)      + (size_t)row * V4;

    const float t_raw = temps[row];
    const float inv   = 1.0f / fmaxf(t_raw, 1e-6f);
    const bool  need_greedy = (t_raw <= 1e-6f);

    const int q0 = seg * SEG_Q;
    const int q1 = q0 + SEG_Q;

    float bg = __int_as_float(0xFF800000);  int bgi = 0;
    float bs = __int_as_float(0xFF800000);  int bsi = 0;

    if (need_greedy) {
        // Rare path (temps ~ U[0,1)): also track raw-logits argmax
        for (int q = q0 + threadIdx.x; q < q1; q += THREADS) {
            float4 l4 = ldg_stream256(lg + q);
            float4 u4 = ldg_stream256(uu + q);
            const int base = q << 2;
            float lv[4] = {l4.x, l4.y, l4.z, l4.w};
            #pragma unroll
            for (int j = 0; j < 4; j++)
                if (lv[j] > bg) { bg = lv[j]; bgi = base + j; }
            body4(l4, u4, base, inv, bs, bsi);
        }
    } else {
        // Software pipeline + L2 prefetch stream PF_DIST iterations ahead:
        // keeps the DRAM request queue continuously fed while demand loads
        // hit L2.
        int q = q0 + threadIdx.x;               // always < q1 (THREADS <= SEG_Q)
        float4 lc = ldg_stream256(lg + q);
        float4 uc = ldg_stream256(uu + q);
        for (int qn = q + THREADS; qn < q1; qn += THREADS) {
            int qpf = min(qn + (PF_DIST - 1) * THREADS, V4 - 1);  // stay in-row
            prefetch_l2(lg + qpf);
            prefetch_l2(uu + qpf);
            float4 ln = ldg_stream256(lg + qn);
            float4 un = ldg_stream256(uu + qn);
            body4(lc, uc, q << 2, inv, bs, bsi);
            lc = ln; uc = un; q = qn;
        }
        body4(lc, uc, q << 2, inv, bs, bsi);
    }

    // Block reduction on packed keys
    unsigned long long kg = pack_key(bg, bgi);
    unsigned long long ks = pack_key(bs, bsi);

    #pragma unroll
    for (int o = 16; o > 0; o >>= 1) {
        kg = kmax64(kg, __shfl_xor_sync(0xffffffffu, kg, o));
        ks = kmax64(ks, __shfl_xor_sync(0xffffffffu, ks, o));
    }

    __shared__ unsigned long long sg[THREADS / 32];
    __shared__ unsigned long long ss[THREADS / 32];
    const int wid  = threadIdx.x >> 5;
    const int lane = threadIdx.x & 31;
    if (lane == 0) { sg[wid] = kg; ss[wid] = ks; }
    __syncthreads();

    if (threadIdx.x == 0) {
        #pragma unroll
        for (int i = 1; i < THREADS / 32; i++) {
            kg = kmax64(kg, sg[i]);
            ks = kmax64(ks, ss[i]);
        }
        d_part_g[row * SPLIT + seg] = kg;
        d_part_s[row * SPLIT + seg] = ks;

        __threadfence();                       // publish partials
        int old = atomicAdd(&d_count[row], 1);
        if (old == SPLIT - 1) {
            d_count[row] = 0;                  // self-reset for next replay
            __threadfence();
            unsigned long long mg = 0ull, ms = 0ull;
            #pragma unroll
            for (int i = 0; i < SPLIT; i++) {
                mg = kmax64(mg, d_part_g[row * SPLIT + i]);
                ms = kmax64(ms, d_part_s[row * SPLIT + i]);
            }
            int ig = (int)~(unsigned int)mg;
            int is = (int)~(unsigned int)ms;
            out[row] = (float)(need_greedy ? ig : is);
        }
    }
}

extern "C" void kernel_launch(void* const* d_in, const int* in_sizes, int n_in,
                              void* d_out, int out_size) {
    const float* logits = (const float*)d_in[0];
    const float* temps  = (const float*)d_in[1];
    const float* u      = (const float*)d_in[2];
    float* out = (float*)d_out;

    dim3 grid(SPLIT, B_ROWS);
    sampler_fused_kernel<<<grid, THREADS>>>(logits, temps, u, out);
}